// round 4
// baseline (speedup 1.0000x reference)
#include <cuda_runtime.h>
#include <cuda_bf16.h>
#include <cstdint>

// Blockwise 8x8 2D DCT, out = D @ X @ D^T over [16,32,512,512] fp32.
// Warp-autonomous, one-transpose dataflow:
//   lane = (octet o = lane>>3, row r = lane&7) of an 8x32 tile (4 blocks/warp)
//   2x LDG.128: lane loads its entire block row (8 floats, 16B-aligned)
//   horizontal DCT on the row (register-resident)
//   one octet XOR-shuffle transpose (12 SHFL)
//   vertical DCT (lane now = column)
//   8 coalesced scalar STG.32 (warp covers full 128B line per row)
// 4 tiles/warp, software-pipelined loads. No smem, no barriers.

#define C0f 0.35355339059327373f  // sqrt(1/8)
#define C1f 0.49039264020161522f  // 0.5*cos(1*pi/16)
#define C2f 0.46193976625564338f  // 0.5*cos(2*pi/16)
#define C3f 0.41573480615127262f  // 0.5*cos(3*pi/16)
#define C4f 0.35355339059327379f  // 0.5*cos(4*pi/16)
#define C5f 0.27778511650980111f  // 0.5*cos(5*pi/16)
#define C6f 0.19134171618254489f  // 0.5*cos(6*pi/16)
#define C7f 0.09754516100806413f  // 0.5*cos(7*pi/16)

__device__ __forceinline__ void dct8(const float x[8], float y[8])
{
    const float s0 = x[0] + x[7], s1 = x[1] + x[6];
    const float s2 = x[2] + x[5], s3 = x[3] + x[4];
    const float d0 = x[0] - x[7], d1 = x[1] - x[6];
    const float d2 = x[2] - x[5], d3 = x[3] - x[4];

    const float a = s0 + s3, b = s1 + s2;
    const float e = s0 - s3, f = s1 - s2;

    y[0] = C0f * (a + b);
    y[4] = C4f * (a - b);
    y[2] = fmaf(C2f, e,  C6f * f);
    y[6] = fmaf(C6f, e, -C2f * f);

    y[1] = fmaf(C1f, d0, fmaf( C3f, d1, fmaf( C5f, d2,  C7f * d3)));
    y[3] = fmaf(C3f, d0, fmaf(-C7f, d1, fmaf(-C1f, d2, -C5f * d3)));
    y[5] = fmaf(C5f, d0, fmaf(-C1f, d1, fmaf( C7f, d2,  C3f * d3)));
    y[7] = fmaf(C7f, d0, fmaf(-C5f, d1, fmaf( C3f, d2, -C1f * d3)));
}

// Octet-local 8x8 transpose: v[r]@lane p  <->  v[p]@lane r  (within each 8-lane octet).
__device__ __forceinline__ void transpose8(float v[8], unsigned lane)
{
    #pragma unroll
    for (int m = 1; m < 8; m <<= 1) {
        const bool hi = (lane & m) != 0;
        #pragma unroll
        for (int r0 = 0; r0 < 8; r0++) {
            if (r0 & m) continue;
            const int r1 = r0 | m;
            float send = hi ? v[r0] : v[r1];
            float recv = __shfl_xor_sync(0xffffffffu, send, m, 32);
            if (hi) v[r0] = recv; else v[r1] = recv;
        }
    }
}

#define W_DIM 512
#define TPW 4   // 8x32 tiles per warp, software-pipelined

__device__ __forceinline__ size_t tile_base(unsigned tid)
{
    // 16 tiles across a 512-wide strip of 8 rows
    return (size_t)(tid >> 4) * (8u * W_DIM) + (size_t)((tid & 15u) << 5);
}

__global__ __launch_bounds__(256)
void dct8x8_kernel(const float* __restrict__ x, float* __restrict__ out)
{
    const unsigned lane = threadIdx.x & 31u;
    const unsigned oct8 = (lane >> 3) << 3;   // octet * 8 (column group offset)
    const unsigned row  = lane & 7u;          // block row this lane loads
    const unsigned warp = blockIdx.x * (blockDim.x >> 5) + (threadIdx.x >> 5);
    unsigned tile = warp * TPW;

    float4 curA, curB;
    {
        const float* __restrict__ p = x + tile_base(tile) + (size_t)row * W_DIM + oct8;
        curA = __ldcs(reinterpret_cast<const float4*>(p));
        curB = __ldcs(reinterpret_cast<const float4*>(p + 4));
    }

    #pragma unroll
    for (int t = 0; t < TPW; t++) {
        float4 nxtA, nxtB;
        if (t + 1 < TPW) {
            const float* __restrict__ p = x + tile_base(tile + 1) + (size_t)row * W_DIM + oct8;
            nxtA = __ldcs(reinterpret_cast<const float4*>(p));
            nxtB = __ldcs(reinterpret_cast<const float4*>(p + 4));
        }

        const float xin[8] = {curA.x, curA.y, curA.z, curA.w,
                              curB.x, curB.y, curB.z, curB.w};

        // horizontal DCT: y = row of (X @ D^T)
        float y[8];
        dct8(xin, y);
        // transpose within octet: lane now holds a column of (X @ D^T)
        transpose8(y, lane);
        // vertical DCT: z[k] = out[k][col]
        float z[8];
        dct8(y, z);

        // coalesced scalar stores: per k, warp covers 32 consecutive columns
        float* __restrict__ q = out + tile_base(tile) + oct8 + row;
        #pragma unroll
        for (int k = 0; k < 8; k++) __stcs(q + (size_t)k * W_DIM, z[k]);

        tile++;
        curA = nxtA; curB = nxtB;
    }
}

extern "C" void kernel_launch(void* const* d_in, const int* in_sizes, int n_in,
                              void* d_out, int out_size)
{
    const float* x = (const float*)d_in[0];
    float* out     = (float*)d_out;

    // per CTA: 8 warps * TPW tiles * 256 elements = 8192 elements
    const int grid = out_size / (256 * TPW * 8);
    dct8x8_kernel<<<grid, 256>>>(x, out);
}

// round 5
// speedup vs baseline: 1.0239x; 1.0239x over previous
#include <cuda_runtime.h>
#include <cuda_bf16.h>
#include <cstdint>

// Blockwise 8x8 2D DCT, out = D @ X @ D^T over [16,32,512,512] fp32.
// Warp-autonomous, single-transpose dataflow with clean loads:
//   lane = column of an 8x32 tile (4 DCT blocks / warp)
//   8 coalesced scalar LDG (each = one full 128B line per warp)
//   vertical butterfly DCT per lane (no shuffles)
//   ONE octet XOR-shuffle transpose (lane -> block row)
//   horizontal butterfly DCT per lane
//   2x STG.128 per lane (fire-and-forget; L2 merges sector halves)
// 8 tiles per warp, software-pipelined loads. No smem, no barriers.

#define C0f 0.35355339059327373f  // sqrt(1/8)
#define C1f 0.49039264020161522f  // 0.5*cos(1*pi/16)
#define C2f 0.46193976625564338f  // 0.5*cos(2*pi/16)
#define C3f 0.41573480615127262f  // 0.5*cos(3*pi/16)
#define C4f 0.35355339059327379f  // 0.5*cos(4*pi/16)
#define C5f 0.27778511650980111f  // 0.5*cos(5*pi/16)
#define C6f 0.19134171618254489f  // 0.5*cos(6*pi/16)
#define C7f 0.09754516100806413f  // 0.5*cos(7*pi/16)

__device__ __forceinline__ void dct8(const float x[8], float y[8])
{
    const float s0 = x[0] + x[7], s1 = x[1] + x[6];
    const float s2 = x[2] + x[5], s3 = x[3] + x[4];
    const float d0 = x[0] - x[7], d1 = x[1] - x[6];
    const float d2 = x[2] - x[5], d3 = x[3] - x[4];

    const float a = s0 + s3, b = s1 + s2;
    const float e = s0 - s3, f = s1 - s2;

    y[0] = C0f * (a + b);
    y[4] = C4f * (a - b);
    y[2] = fmaf(C2f, e,  C6f * f);
    y[6] = fmaf(C6f, e, -C2f * f);

    y[1] = fmaf(C1f, d0, fmaf( C3f, d1, fmaf( C5f, d2,  C7f * d3)));
    y[3] = fmaf(C3f, d0, fmaf(-C7f, d1, fmaf(-C1f, d2, -C5f * d3)));
    y[5] = fmaf(C5f, d0, fmaf(-C1f, d1, fmaf( C7f, d2,  C3f * d3)));
    y[7] = fmaf(C7f, d0, fmaf( C3f, d2, fmaf(-C5f, d1, -C1f * d3)));
}

// Octet-local 8x8 transpose: after call, lane p holds (at index i) the value
// that lane (oct(p)*8 + i) held at index (p&7) before the call.
__device__ __forceinline__ void transpose8(float v[8], unsigned lane)
{
    #pragma unroll
    for (int m = 1; m < 8; m <<= 1) {
        const bool hi = (lane & m) != 0;
        #pragma unroll
        for (int r0 = 0; r0 < 8; r0++) {
            if (r0 & m) continue;
            const int r1 = r0 | m;
            float send = hi ? v[r0] : v[r1];
            float recv = __shfl_xor_sync(0xffffffffu, send, m, 32);
            if (hi) v[r0] = recv; else v[r1] = recv;
        }
    }
}

#define W_DIM 512
#define TPW 8   // 8x32 tiles per warp, software-pipelined

__device__ __forceinline__ size_t tile_base(unsigned tid)
{
    // 16 tiles across a 512-wide strip of 8 rows
    return (size_t)(tid >> 4) * (8u * W_DIM) + (size_t)((tid & 15u) << 5);
}

__global__ __launch_bounds__(256)
void dct8x8_kernel(const float* __restrict__ x, float* __restrict__ out)
{
    const unsigned lane = threadIdx.x & 31u;
    const unsigned oct8 = lane & 24u;   // (lane>>3)*8
    const unsigned row  = lane & 7u;
    const unsigned warp = blockIdx.x * (blockDim.x >> 5) + (threadIdx.x >> 5);
    unsigned tile = warp * TPW;

    float cur[8];
    {
        const float* __restrict__ p = x + tile_base(tile) + lane;
        #pragma unroll
        for (int i = 0; i < 8; i++) cur[i] = __ldcs(p + (size_t)i * W_DIM);
    }

    #pragma unroll
    for (int t = 0; t < TPW; t++) {
        float nxt[8];
        if (t + 1 < TPW) {
            const float* __restrict__ p = x + tile_base(tile + 1) + lane;
            #pragma unroll
            for (int i = 0; i < 8; i++) nxt[i] = __ldcs(p + (size_t)i * W_DIM);
        }

        // vertical DCT (lane = column, regs = rows)
        float y[8];
        dct8(cur, y);
        // one transpose: lane now holds row (lane&7) of block (lane>>3),
        // regs = that row's 8 columns
        transpose8(y, lane);
        // horizontal DCT on the register-resident row
        float z[8];
        dct8(y, z);

        // 2x STG.128: both halves of each 32B sector written by this warp
        // back-to-back; L2 merges to full lines before writeback.
        float* __restrict__ q = out + tile_base(tile) + (size_t)row * W_DIM + oct8;
        __stcs(reinterpret_cast<float4*>(q),     make_float4(z[0], z[1], z[2], z[3]));
        __stcs(reinterpret_cast<float4*>(q + 4), make_float4(z[4], z[5], z[6], z[7]));

        tile++;
        #pragma unroll
        for (int i = 0; i < 8; i++) cur[i] = nxt[i];
    }
}

extern "C" void kernel_launch(void* const* d_in, const int* in_sizes, int n_in,
                              void* d_out, int out_size)
{
    const float* x = (const float*)d_in[0];
    float* out     = (float*)d_out;

    // per CTA: 8 warps * TPW tiles * 256 elements
    const int grid = out_size / (256 * TPW * 8);
    dct8x8_kernel<<<grid, 256>>>(x, out);
}

// round 6
// speedup vs baseline: 1.1010x; 1.0753x over previous
#include <cuda_runtime.h>
#include <cuda_bf16.h>
#include <cstdint>

// Blockwise 8x8 2D DCT, out = D @ X @ D^T over [16,32,512,512] fp32.
// Round-3 dataflow (all gmem accesses warp-covers-full-128B-lines), with the
// second shuffle transpose replaced by a conflict-free warp-private smem
// bounce (2x STS.128 + 8 LDS), cutting ~24 SEL + 12 SHFL per tile.
//   lane = column of an 8x32 tile (4 DCT blocks / warp)
//   8 coalesced scalar LDG -> vertical DCT (lane = col)
//   octet XOR-shuffle transpose -> lane (b,r) holds block row
//   horizontal DCT -> z[l] = out[r][8b+l]
//   STS.128 x2 into buf[r*36 + 8b..], __syncwarp
//   LDS x8 by column -> 8 coalesced scalar STG
// 4 tiles per warp, software-pipelined loads. No __syncthreads.

#define C0f 0.35355339059327373f  // sqrt(1/8)
#define C1f 0.49039264020161522f  // 0.5*cos(1*pi/16)
#define C2f 0.46193976625564338f  // 0.5*cos(2*pi/16)
#define C3f 0.41573480615127262f  // 0.5*cos(3*pi/16)
#define C4f 0.35355339059327379f  // 0.5*cos(4*pi/16)
#define C5f 0.27778511650980111f  // 0.5*cos(5*pi/16)
#define C6f 0.19134171618254489f  // 0.5*cos(6*pi/16)
#define C7f 0.09754516100806413f  // 0.5*cos(7*pi/16)

__device__ __forceinline__ void dct8(const float x[8], float y[8])
{
    const float s0 = x[0] + x[7], s1 = x[1] + x[6];
    const float s2 = x[2] + x[5], s3 = x[3] + x[4];
    const float d0 = x[0] - x[7], d1 = x[1] - x[6];
    const float d2 = x[2] - x[5], d3 = x[3] - x[4];

    const float a = s0 + s3, b = s1 + s2;
    const float e = s0 - s3, f = s1 - s2;

    y[0] = C0f * (a + b);
    y[4] = C4f * (a - b);
    y[2] = fmaf(C2f, e,  C6f * f);
    y[6] = fmaf(C6f, e, -C2f * f);

    y[1] = fmaf(C1f, d0, fmaf( C3f, d1, fmaf( C5f, d2,  C7f * d3)));
    y[3] = fmaf(C3f, d0, fmaf(-C7f, d1, fmaf(-C1f, d2, -C5f * d3)));
    y[5] = fmaf(C5f, d0, fmaf(-C1f, d1, fmaf( C7f, d2,  C3f * d3)));
    y[7] = fmaf(C7f, d0, fmaf(-C5f, d1, fmaf( C3f, d2, -C1f * d3)));
}

// Octet-local 8x8 transpose (12 SHFL): after call, lane p holds at index i the
// value lane (oct(p)*8 + i) held at index (p&7).
__device__ __forceinline__ void transpose8(float v[8], unsigned lane)
{
    #pragma unroll
    for (int m = 1; m < 8; m <<= 1) {
        const bool hi = (lane & m) != 0;
        #pragma unroll
        for (int r0 = 0; r0 < 8; r0++) {
            if (r0 & m) continue;
            const int r1 = r0 | m;
            float send = hi ? v[r0] : v[r1];
            float recv = __shfl_xor_sync(0xffffffffu, send, m, 32);
            if (hi) v[r0] = recv; else v[r1] = recv;
        }
    }
}

#define W_DIM 512
#define TPW 4           // 8x32 tiles per warp, software-pipelined
#define ROWSTRIDE 36    // floats per buffered row (32 + 4 pad, 16B multiple)

__device__ __forceinline__ size_t tile_base(unsigned tid)
{
    // 16 tiles across a 512-wide strip of 8 rows
    return (size_t)(tid >> 4) * (8u * W_DIM) + (size_t)((tid & 15u) << 5);
}

__global__ __launch_bounds__(256)
void dct8x8_kernel(const float* __restrict__ x, float* __restrict__ out)
{
    __shared__ float buf_all[8][8 * ROWSTRIDE];   // per-warp private buffers
    float* __restrict__ buf = buf_all[threadIdx.x >> 5];

    const unsigned lane = threadIdx.x & 31u;
    const unsigned oct8 = lane & 24u;   // block index * 8
    const unsigned row  = lane & 7u;    // row within block (after transpose)
    const unsigned warp = blockIdx.x * (blockDim.x >> 5) + (threadIdx.x >> 5);
    unsigned tile = warp * TPW;

    float cur[8];
    {
        const float* __restrict__ p = x + tile_base(tile) + lane;
        #pragma unroll
        for (int i = 0; i < 8; i++) cur[i] = __ldcs(p + (size_t)i * W_DIM);
    }

    #pragma unroll
    for (int t = 0; t < TPW; t++) {
        float nxt[8];
        if (t + 1 < TPW) {
            const float* __restrict__ p = x + tile_base(tile + 1) + lane;
            #pragma unroll
            for (int i = 0; i < 8; i++) nxt[i] = __ldcs(p + (size_t)i * W_DIM);
        }

        // vertical DCT (lane = column, regs = rows)
        float y[8];
        dct8(cur, y);
        // transpose: lane (b = lane>>3, r = lane&7) now holds block row r
        transpose8(y, lane);
        // horizontal DCT: z[l] = out[r][8b + l] (local columns)
        float z[8];
        dct8(y, z);

        // stash output rows in smem (row stride 36 floats, 4-way-perfect banks)
        float* __restrict__ q = buf + row * ROWSTRIDE + oct8;
        *reinterpret_cast<float4*>(q)     = make_float4(z[0], z[1], z[2], z[3]);
        *reinterpret_cast<float4*>(q + 4) = make_float4(z[4], z[5], z[6], z[7]);
        __syncwarp();

        // gather by column (conflict-free) and store clean full-line rows
        float* __restrict__ o = out + tile_base(tile) + lane;
        #pragma unroll
        for (int k = 0; k < 8; k++)
            __stcs(o + (size_t)k * W_DIM, buf[k * ROWSTRIDE + lane]);
        __syncwarp();   // WAR guard before next tile's STS

        tile++;
        #pragma unroll
        for (int i = 0; i < 8; i++) cur[i] = nxt[i];
    }
}

extern "C" void kernel_launch(void* const* d_in, const int* in_sizes, int n_in,
                              void* d_out, int out_size)
{
    const float* x = (const float*)d_in[0];
    float* out     = (float*)d_out;

    // per CTA: 8 warps * TPW tiles * 256 elements
    const int grid = out_size / (256 * TPW * 8);
    dct8x8_kernel<<<grid, 256>>>(x, out);
}

// round 7
// speedup vs baseline: 1.1063x; 1.0049x over previous
#include <cuda_runtime.h>
#include <cuda_bf16.h>
#include <cstdint>

// Blockwise 8x8 2D DCT, out = D @ X @ D^T over [16,32,512,512] fp32.
// All gmem accesses are warp-covers-full-128B-lines (proven in R3/R6).
// BOTH transposes are now conflict-free warp-private smem bounces:
//   8 coalesced scalar LDG (lane = column of an 8x32 tile)
//   vertical butterfly DCT
//   bounce 1: 8x STS.32 (banks 4k+lane, CF) -> 2x LDS.128 (row gather, CF)
//   horizontal butterfly DCT
//   bounce 2: 2x STS.128 (CF) -> 8x LDS.32 by column (CF)
//   8 coalesced scalar STG
// 4 tiles per warp, software-pipelined loads. No __syncthreads, no shuffles.

#define C0f 0.35355339059327373f  // sqrt(1/8)
#define C1f 0.49039264020161522f  // 0.5*cos(1*pi/16)
#define C2f 0.46193976625564338f  // 0.5*cos(2*pi/16)
#define C3f 0.41573480615127262f  // 0.5*cos(3*pi/16)
#define C4f 0.35355339059327379f  // 0.5*cos(4*pi/16)
#define C5f 0.27778511650980111f  // 0.5*cos(5*pi/16)
#define C6f 0.19134171618254489f  // 0.5*cos(6*pi/16)
#define C7f 0.09754516100806413f  // 0.5*cos(7*pi/16)

__device__ __forceinline__ void dct8(const float x[8], float y[8])
{
    const float s0 = x[0] + x[7], s1 = x[1] + x[6];
    const float s2 = x[2] + x[5], s3 = x[3] + x[4];
    const float d0 = x[0] - x[7], d1 = x[1] - x[6];
    const float d2 = x[2] - x[5], d3 = x[3] - x[4];

    const float a = s0 + s3, b = s1 + s2;
    const float e = s0 - s3, f = s1 - s2;

    y[0] = C0f * (a + b);
    y[4] = C4f * (a - b);
    y[2] = fmaf(C2f, e,  C6f * f);
    y[6] = fmaf(C6f, e, -C2f * f);

    y[1] = fmaf(C1f, d0, fmaf( C3f, d1, fmaf( C5f, d2,  C7f * d3)));
    y[3] = fmaf(C3f, d0, fmaf(-C7f, d1, fmaf(-C1f, d2, -C5f * d3)));
    y[5] = fmaf(C5f, d0, fmaf(-C1f, d1, fmaf( C7f, d2,  C3f * d3)));
    y[7] = fmaf(C7f, d0, fmaf(-C5f, d1, fmaf( C3f, d2, -C1f * d3)));
}

#define W_DIM 512
#define TPW 4           // 8x32 tiles per warp, software-pipelined
#define RS 36           // row stride in floats (32 + 4 pad; multiple of 4 for .128)

__device__ __forceinline__ size_t tile_base(unsigned tid)
{
    // 16 tiles across a 512-wide strip of 8 rows
    return (size_t)(tid >> 4) * (8u * W_DIM) + (size_t)((tid & 15u) << 5);
}

__global__ __launch_bounds__(256)
void dct8x8_kernel(const float* __restrict__ x, float* __restrict__ out)
{
    // two warp-private bounce buffers per warp, 8*RS floats each
    __shared__ float buf1_all[8][8 * RS];
    __shared__ float buf2_all[8][8 * RS];
    const unsigned wq = threadIdx.x >> 5;
    float* __restrict__ buf1 = buf1_all[wq];
    float* __restrict__ buf2 = buf2_all[wq];

    const unsigned lane = threadIdx.x & 31u;
    const unsigned oct8 = lane & 24u;   // block index * 8
    const unsigned row  = lane & 7u;    // row within block
    const unsigned warp = blockIdx.x * (blockDim.x >> 5) + wq;
    unsigned tile = warp * TPW;

    float cur[8];
    {
        const float* __restrict__ p = x + tile_base(tile) + lane;
        #pragma unroll
        for (int i = 0; i < 8; i++) cur[i] = __ldcs(p + (size_t)i * W_DIM);
    }

    #pragma unroll
    for (int t = 0; t < TPW; t++) {
        float nxt[8];
        if (t + 1 < TPW) {
            const float* __restrict__ p = x + tile_base(tile + 1) + lane;
            #pragma unroll
            for (int i = 0; i < 8; i++) nxt[i] = __ldcs(p + (size_t)i * W_DIM);
        }

        // vertical DCT (lane = column, regs = rows)
        float y[8];
        dct8(cur, y);

        // ---- bounce 1: k-major scatter, row-major gather (both CF) ----
        #pragma unroll
        for (int k = 0; k < 8; k++) buf1[k * RS + lane] = y[k];
        __syncwarp();   // also covers cross-iter WAR on buf2

        float rowv[8];
        {
            const float4 a = *reinterpret_cast<const float4*>(buf1 + row * RS + oct8);
            const float4 b = *reinterpret_cast<const float4*>(buf1 + row * RS + oct8 + 4);
            rowv[0] = a.x; rowv[1] = a.y; rowv[2] = a.z; rowv[3] = a.w;
            rowv[4] = b.x; rowv[5] = b.y; rowv[6] = b.z; rowv[7] = b.w;
        }

        // horizontal DCT on the register-resident row
        float z[8];
        dct8(rowv, z);

        // ---- bounce 2: row-major scatter, column gather (both CF) ----
        {
            float* __restrict__ q = buf2 + row * RS + oct8;
            *reinterpret_cast<float4*>(q)     = make_float4(z[0], z[1], z[2], z[3]);
            *reinterpret_cast<float4*>(q + 4) = make_float4(z[4], z[5], z[6], z[7]);
        }
        __syncwarp();   // also covers cross-iter WAR on buf1

        float* __restrict__ o = out + tile_base(tile) + lane;
        #pragma unroll
        for (int k = 0; k < 8; k++)
            __stcs(o + (size_t)k * W_DIM, buf2[k * RS + lane]);

        tile++;
        #pragma unroll
        for (int i = 0; i < 8; i++) cur[i] = nxt[i];
    }
}

extern "C" void kernel_launch(void* const* d_in, const int* in_sizes, int n_in,
                              void* d_out, int out_size)
{
    const float* x = (const float*)d_in[0];
    float* out     = (float*)d_out;

    // per CTA: 8 warps * TPW tiles * 256 elements
    const int grid = out_size / (256 * TPW * 8);
    dct8x8_kernel<<<grid, 256>>>(x, out);
}